// round 9
// baseline (speedup 1.0000x reference)
#include <cuda_runtime.h>

// BatchDelayProcessor: lag-D feedback delay line.
//   c_k = x_k + FB * c_{k-1}         (carry per chain, c_{-1} = 0)
//   out_k = (1-MIX) * x_k + MIX * c_{k-1}
// Each (b, j) with j in [0, D) is an independent length-NBLK chain.
//
// R8: all cache/scheduling probes were neutral -> kernel is pinned at
// 226MB/replay of DRAM traffic. Remaining lever: wave shape. 2757 CTAs was
// 2.33 waves at occ=8 -> ragged tail. Persistent single-wave launch:
// 148 SMs x 8 CTAs = 1184 CTAs, grid-stride over chains, perfect balance,
// zero wave transitions.

#define D_SAMP   22050
#define T_LEN    441000
#define B_SZ     64
#define NBLK     20          // T_LEN / D_SAMP
#define FB       0.3f
#define MIXC     0.5f

#define HD       (D_SAMP / 2)            // 11025 float2 chains per batch row
#define NCHAINS  (B_SZ * HD)             // 705600 (fits in int)

#define GRID_CTAS   1184                 // 148 SMs * 8 resident CTAs
#define CTA_THREADS 256

__global__ __launch_bounds__(CTA_THREADS) void delay_kernel(const float* __restrict__ x,
                                                            float* __restrict__ out) {
    const int stride = GRID_CTAS * CTA_THREADS;      // 303104

    for (int idx = blockIdx.x * CTA_THREADS + threadIdx.x;
         idx < NCHAINS; idx += stride) {

        int b = idx / HD;
        int j = (idx - b * HD) * 2;

        const float2* __restrict__ xp =
            (const float2*)(x + (size_t)b * T_LEN + j);
        float2* __restrict__ op =
            (float2*)(out + (size_t)b * T_LEN + j);

        float cx = 0.0f, cy = 0.0f;

#pragma unroll
        for (int k = 0; k < NBLK; k++) {
            // element stride between k-blocks: D_SAMP floats = HD float2
            float2 xv = xp[(size_t)k * HD];
            float2 o;
            o.x = fmaf(cx, MIXC, xv.x * (1.0f - MIXC));
            o.y = fmaf(cy, MIXC, xv.y * (1.0f - MIXC));
            op[(size_t)k * HD] = o;
            cx = fmaf(cx, FB, xv.x);
            cy = fmaf(cy, FB, xv.y);
        }
    }
}

extern "C" void kernel_launch(void* const* d_in, const int* in_sizes, int n_in,
                              void* d_out, int out_size) {
    const float* x = (const float*)d_in[0];
    float* out = (float*)d_out;
    delay_kernel<<<GRID_CTAS, CTA_THREADS>>>(x, out);
}

// round 10
// speedup vs baseline: 1.0864x; 1.0864x over previous
#include <cuda_runtime.h>

// BatchDelayProcessor: lag-D feedback delay line.
//   c_k = x_k + FB * c_{k-1}         (carry per chain, c_{-1} = 0)
//   out_k = (1-MIX) * x_k + MIX * c_{k-1}
// Each (b, j) with j in [0, D) is an independent length-NBLK chain:
// one thread owns one float2 chain, fully unrolled over the 20 k-blocks.
//
// R9 (final): revert to the best-measured variant (R0, 39.36us).
// Exhaustive probes — front-batched MLP, L2 evict_last/evict_first policies,
// .cs/.wt stores, smem-staged 128-bit accesses, persistent single-wave
// grid — were all neutral or regressions. Steady-state replay traffic is
// compulsory (226 MB: input re-read + output writeback; dirty out lines
// evict x from L2 and replacement hints are inert at default carveout), and
// ~5.7 TB/s is the achieved mixed-R/W HBM ceiling. This kernel sits on that
// roofline.

#define D_SAMP   22050
#define T_LEN    441000
#define B_SZ     64
#define NBLK     20          // T_LEN / D_SAMP
#define FB       0.3f
#define MIXC     0.5f

// float2 vectorization: D_SAMP % 2 == 0
#define HD       (D_SAMP / 2)                 // 11025 float2 chains per batch row
#define NCHAINS  ((long long)B_SZ * HD)       // 705600

__global__ __launch_bounds__(256) void delay_kernel(const float* __restrict__ x,
                                                    float* __restrict__ out) {
    long long idx = (long long)blockIdx.x * blockDim.x + threadIdx.x;
    if (idx >= NCHAINS) return;

    int b = (int)(idx / HD);
    int j = (int)(idx % HD) * 2;

    const char* xbase = (const char*)(x + (size_t)b * T_LEN + j);
    char*       obase = (char*)(out + (size_t)b * T_LEN + j);

    float2 c;
    c.x = 0.0f;
    c.y = 0.0f;

    const size_t blk_stride = (size_t)D_SAMP * sizeof(float);  // 88200 B

#pragma unroll
    for (int k = 0; k < NBLK; k++) {
        float2 xv = *reinterpret_cast<const float2*>(xbase + (size_t)k * blk_stride);
        float2 o;
        // out = x*(1-MIX) + c*MIX
        o.x = fmaf(c.x, MIXC, xv.x * (1.0f - MIXC));
        o.y = fmaf(c.y, MIXC, xv.y * (1.0f - MIXC));
        *reinterpret_cast<float2*>(obase + (size_t)k * blk_stride) = o;
        // c = x + FB*c
        c.x = fmaf(c.x, FB, xv.x);
        c.y = fmaf(c.y, FB, xv.y);
    }
}

extern "C" void kernel_launch(void* const* d_in, const int* in_sizes, int n_in,
                              void* d_out, int out_size) {
    const float* x = (const float*)d_in[0];
    float* out = (float*)d_out;

    const int threads = 256;
    const long long nthreads = NCHAINS;
    const int blocks = (int)((nthreads + threads - 1) / threads);
    delay_kernel<<<blocks, threads>>>(x, out);
}

// round 11
// speedup vs baseline: 1.0934x; 1.0065x over previous
#include <cuda_runtime.h>

// BatchDelayProcessor: lag-D feedback delay line.
//   c_k = x_k + FB * c_{k-1}         (carry per chain, c_{-1} = 0)
//   out_k = (1-MIX) * x_k + MIX * c_{k-1}
// Each (b, j) with j in [0, D) is an independent length-NBLK chain:
// one thread owns one float2 chain, fully unrolled over the 20 k-blocks.
//
// Final form. Roofline analysis: steady-state graph-replay traffic is
// compulsory 226 MB (113 MB input re-read — dirty output evicts x from the
// 126 MB L2 and replacement hints are inert at default carveout — plus
// 113 MB output writeback). Achieved mixed-R/W HBM bandwidth ceiling is
// ~5.7 TB/s => ~39.4us. All probes (evict policies, .cs/.wt stores,
// front-batched MLP, smem-staged 128-bit, persistent grid) were neutral or
// regressions. R10: block=512 (oe 8->4 reduces cross-CTA L1tex spread) is
// the last noise-level knob.

#define D_SAMP   22050
#define T_LEN    441000
#define B_SZ     64
#define NBLK     20          // T_LEN / D_SAMP
#define FB       0.3f
#define MIXC     0.5f

// float2 vectorization: D_SAMP % 2 == 0
#define HD       (D_SAMP / 2)            // 11025 float2 chains per batch row
#define NCHAINS  (B_SZ * HD)             // 705600 (fits in int)

#define CTA_THREADS 512

__global__ __launch_bounds__(CTA_THREADS) void delay_kernel(const float* __restrict__ x,
                                                            float* __restrict__ out) {
    int idx = blockIdx.x * CTA_THREADS + threadIdx.x;
    if (idx >= NCHAINS) return;

    int b = idx / HD;
    int j = (idx - b * HD) * 2;

    const char* xbase = (const char*)(x + (size_t)b * T_LEN + j);
    char*       obase = (char*)(out + (size_t)b * T_LEN + j);

    float2 c;
    c.x = 0.0f;
    c.y = 0.0f;

    const size_t blk_stride = (size_t)D_SAMP * sizeof(float);  // 88200 B

#pragma unroll
    for (int k = 0; k < NBLK; k++) {
        float2 xv = *reinterpret_cast<const float2*>(xbase + (size_t)k * blk_stride);
        float2 o;
        // out = x*(1-MIX) + c*MIX
        o.x = fmaf(c.x, MIXC, xv.x * (1.0f - MIXC));
        o.y = fmaf(c.y, MIXC, xv.y * (1.0f - MIXC));
        *reinterpret_cast<float2*>(obase + (size_t)k * blk_stride) = o;
        // c = x + FB*c
        c.x = fmaf(c.x, FB, xv.x);
        c.y = fmaf(c.y, FB, xv.y);
    }
}

extern "C" void kernel_launch(void* const* d_in, const int* in_sizes, int n_in,
                              void* d_out, int out_size) {
    const float* x = (const float*)d_in[0];
    float* out = (float*)d_out;

    const int blocks = (NCHAINS + CTA_THREADS - 1) / CTA_THREADS;  // 1379
    delay_kernel<<<blocks, CTA_THREADS>>>(x, out);
}